// round 2
// baseline (speedup 1.0000x reference)
#include <cuda_runtime.h>
#include <math.h>

#define H 1024
#define E 8
#define T_TOK 8192
#define MAXR 16384   // total routed rows across all experts is exactly 2*T_TOK

// ---- scratch (device globals: allocation-free rule) ----
__device__ int   d_counts[E];
__device__ int   d_tok[E * MAXR];
__device__ float d_gate[E * MAXR];

__global__ void zero_counts_k() {
    if (threadIdx.x < E) d_counts[threadIdx.x] = 0;
}

// One warp per token: 8 logits, top-2, gates, compaction.
__global__ void router_k(const float* __restrict__ x, const float* __restrict__ Wg) {
    int gwarp = (blockIdx.x * blockDim.x + threadIdx.x) >> 5;
    int lane  = threadIdx.x & 31;
    if (gwarp >= T_TOK) return;
    const float* xr = x + (size_t)gwarp * H;

    float acc[E];
#pragma unroll
    for (int e = 0; e < E; e++) acc[e] = 0.f;

#pragma unroll 4
    for (int i = 0; i < H / 32; i++) {
        int h = lane + i * 32;
        float xv = __ldg(&xr[h]);
        float4 w0 = *(const float4*)&Wg[h * E];
        float4 w1 = *(const float4*)&Wg[h * E + 4];
        acc[0] = fmaf(xv, w0.x, acc[0]);
        acc[1] = fmaf(xv, w0.y, acc[1]);
        acc[2] = fmaf(xv, w0.z, acc[2]);
        acc[3] = fmaf(xv, w0.w, acc[3]);
        acc[4] = fmaf(xv, w1.x, acc[4]);
        acc[5] = fmaf(xv, w1.y, acc[5]);
        acc[6] = fmaf(xv, w1.z, acc[6]);
        acc[7] = fmaf(xv, w1.w, acc[7]);
    }
#pragma unroll
    for (int e = 0; e < E; e++) {
#pragma unroll
        for (int o = 16; o > 0; o >>= 1)
            acc[e] += __shfl_xor_sync(0xffffffffu, acc[e], o);
    }

    if (lane == 0) {
        // top-2 of logits (== top-2 of softmax; strict > keeps lower index on tie, matching jax)
        int i0 = 0;
#pragma unroll
        for (int e = 1; e < E; e++) if (acc[e] > acc[i0]) i0 = e;
        int i1 = (i0 == 0) ? 1 : 0;
#pragma unroll
        for (int e = 0; e < E; e++) {
            if (e == i0) continue;
            if (acc[e] > acc[i1]) i1 = e;
        }
        // gates = top_vals / sum(top_vals) == softmax over the two top logits
        float d  = expf(acc[i1] - acc[i0]);
        float s  = 1.f + d;
        float g0 = 1.f / s;
        float g1 = d / s;

        int p0 = atomicAdd(&d_counts[i0], 1);
        d_tok[i0 * MAXR + p0]  = gwarp;
        d_gate[i0 * MAXR + p0] = g0;
        int p1 = atomicAdd(&d_counts[i1], 1);
        d_tok[i1 * MAXR + p1]  = gwarp;
        d_gate[i1 * MAXR + p1] = g1;
    }
}

// Gathered fp32 SGEMM per expert: C[r,:] = x[tok[r],:] @ We[e] (+be), scatter gate*C into out.
// 128x128 tile, BK=8, 256 threads, 8x8 per-thread in 4x4 quadrants.
__global__ __launch_bounds__(256, 2)
void expert_gemm_k(const float* __restrict__ x, const float* __restrict__ We,
                   const float* __restrict__ be, float* __restrict__ out) {
    const int e   = blockIdx.z;
    const int cnt = d_counts[e];
    const int m0  = blockIdx.x * 128;
    if (m0 >= cnt) return;
    const int n0  = blockIdx.y * 128;

    __shared__ float As[8][128];
    __shared__ float Bs[8][128];
    __shared__ int   toks[128];
    __shared__ float gts[128];

    const int tid = threadIdx.x;
    if (tid < 128) {
        int r = m0 + tid;
        toks[tid] = (r < cnt) ? d_tok[e * MAXR + r]  : -1;
        gts[tid]  = (r < cnt) ? d_gate[e * MAXR + r] : 0.f;
    }
    __syncthreads();

    const float* B = We + (size_t)e * H * H + n0;

    const int arow = tid >> 1;            // 0..127
    const int ak   = (tid & 1) * 4;       // 0 or 4
    const int brow = tid >> 5;            // 0..7
    const int bc   = (tid & 31) * 4;      // 0..124
    const int r0   = (tid >> 4) * 4;      // 0..60 (quadrant row base)
    const int c0   = (tid & 15) * 4;      // 0..60 (quadrant col base)

    float acc[8][8];
#pragma unroll
    for (int i = 0; i < 8; i++)
#pragma unroll
        for (int j = 0; j < 8; j++) acc[i][j] = 0.f;

    const int ta = toks[arow];
    const float* xa = &x[(size_t)(ta < 0 ? 0 : ta) * H + ak];

    for (int k0 = 0; k0 < H; k0 += 8) {
        float4 av = (ta >= 0) ? __ldg((const float4*)(xa + k0)) : make_float4(0.f, 0.f, 0.f, 0.f);
        float4 bv = __ldg((const float4*)&B[(size_t)(k0 + brow) * H + bc]);
        As[ak + 0][arow] = av.x;
        As[ak + 1][arow] = av.y;
        As[ak + 2][arow] = av.z;
        As[ak + 3][arow] = av.w;
        *(float4*)&Bs[brow][bc] = bv;
        __syncthreads();

#pragma unroll
        for (int k = 0; k < 8; k++) {
            float a[8], b[8];
            *(float4*)(a)     = *(const float4*)&As[k][r0];
            *(float4*)(a + 4) = *(const float4*)&As[k][r0 + 64];
            *(float4*)(b)     = *(const float4*)&Bs[k][c0];
            *(float4*)(b + 4) = *(const float4*)&Bs[k][c0 + 64];
#pragma unroll
            for (int i = 0; i < 8; i++)
#pragma unroll
                for (int j = 0; j < 8; j++)
                    acc[i][j] = fmaf(a[i], b[j], acc[i][j]);
        }
        __syncthreads();
    }

    // epilogue: out[t, n0+col] += gate * (acc + be[e, n0+col])
    const float* berow = be + e * H + n0;
    float bias[8];
#pragma unroll
    for (int j = 0; j < 8; j++) {
        int lc = c0 + ((j < 4) ? j : 64 + (j - 4));
        bias[j] = __ldg(&berow[lc]);
    }
#pragma unroll
    for (int i = 0; i < 8; i++) {
        int lr = r0 + ((i < 4) ? i : 64 + (i - 4));
        int t  = toks[lr];
        if (t < 0) continue;
        float g = gts[lr];
        float* orow = out + (size_t)t * H + n0;
#pragma unroll
        for (int j = 0; j < 8; j++) {
            int lc = c0 + ((j < 4) ? j : 64 + (j - 4));
            atomicAdd(&orow[lc], g * (acc[i][j] + bias[j]));
        }
    }
}

extern "C" void kernel_launch(void* const* d_in, const int* in_sizes, int n_in,
                              void* d_out, int out_size) {
    const float* x  = (const float*)d_in[0];   // hidden_states (4,2048,1024)
    const float* Wg = (const float*)d_in[1];   // (1024, 8)
    const float* We = (const float*)d_in[2];   // (8, 1024, 1024)
    const float* be = (const float*)d_in[3];   // (8, 1024)
    float* out = (float*)d_out;

    cudaMemsetAsync(out, 0, (size_t)out_size * sizeof(float), 0);
    zero_counts_k<<<1, 32>>>();

    // router: 1 warp/token, 8 warps/block
    router_k<<<T_TOK / 8, 256>>>(x, Wg);

    // expert GEMMs: grid covers worst-case row count per expert; inactive tiles exit early
    dim3 grid(MAXR / 128, H / 128, E);
    expert_gemm_k<<<grid, 256>>>(x, We, be, out);
}

// round 7
// speedup vs baseline: 2.7320x; 2.7320x over previous
#include <cuda_runtime.h>
#include <cuda_bf16.h>
#include <math.h>
#include <stdint.h>

#define H 1024
#define E 8
#define T_TOK 8192
#define MAXR 16384
#define NITER 96            // 3 passes x 32 k-chunks (BK=32 bf16)
#define SMSTRIDE 80         // bytes per SMEM row (64B data + 16B pad, ldmatrix conflict-free)

// ---- device-global scratch (allocation-free rule) ----
__device__ int   d_counts[E];
__device__ int   d_tok[E * MAXR];
__device__ float d_gate[E * MAXR];
__device__ __nv_bfloat16 g_xh[(size_t)T_TOK * H];
__device__ __nv_bfloat16 g_xl[(size_t)T_TOK * H];
__device__ __nv_bfloat16 g_wh[(size_t)E * H * H];   // transposed: [e][n][k]
__device__ __nv_bfloat16 g_wl[(size_t)E * H * H];

__device__ __forceinline__ unsigned smem_u32(const void* p) {
    return (unsigned)__cvta_generic_to_shared(p);
}
__device__ __forceinline__ void ldmatrix_x4(unsigned r[4], unsigned addr) {
    asm volatile("ldmatrix.sync.aligned.m8n8.x4.shared.b16 {%0,%1,%2,%3}, [%4];"
                 : "=r"(r[0]), "=r"(r[1]), "=r"(r[2]), "=r"(r[3]) : "r"(addr));
}
__device__ __forceinline__ void mma_bf16(float d[4], const unsigned a[4],
                                         unsigned b0, unsigned b1) {
    asm volatile(
        "mma.sync.aligned.m16n8k16.row.col.f32.bf16.bf16.f32 "
        "{%0,%1,%2,%3}, {%4,%5,%6,%7}, {%8,%9}, {%0,%1,%2,%3};"
        : "+f"(d[0]), "+f"(d[1]), "+f"(d[2]), "+f"(d[3])
        : "r"(a[0]), "r"(a[1]), "r"(a[2]), "r"(a[3]), "r"(b0), "r"(b1));
}

// ---------------- small kernels ----------------
__global__ void zero_counts_k() {
    if (threadIdx.x < E) d_counts[threadIdx.x] = 0;
}

__global__ void convert_x_k(const float* __restrict__ x) {
    size_t i = ((size_t)blockIdx.x * blockDim.x + threadIdx.x) * 4;
    float4 v = *(const float4*)(x + i);
    __nv_bfloat16 h[4], l[4];
    float f[4] = {v.x, v.y, v.z, v.w};
#pragma unroll
    for (int j = 0; j < 4; j++) {
        h[j] = __float2bfloat16(f[j]);
        l[j] = __float2bfloat16(f[j] - __bfloat162float(h[j]));
    }
    *(uint2*)&g_xh[i] = *(uint2*)h;
    *(uint2*)&g_xl[i] = *(uint2*)l;
}

// We[e][k][n] fp32 -> g_wh/g_wl[e][n][k] bf16 (tiled transpose)
__global__ void convert_we_k(const float* __restrict__ We) {
    __shared__ float t[32][33];
    int e = blockIdx.z, n0 = blockIdx.x * 32, k0 = blockIdx.y * 32;
    const float* W = We + ((size_t)e << 20);
    int tx = threadIdx.x, ty = threadIdx.y;
#pragma unroll
    for (int j = 0; j < 4; j++)
        t[ty + j * 8][tx] = W[(size_t)(k0 + ty + j * 8) * H + n0 + tx];
    __syncthreads();
#pragma unroll
    for (int j = 0; j < 4; j++) {
        float v = t[tx][ty + j * 8];
        __nv_bfloat16 hi = __float2bfloat16(v);
        __nv_bfloat16 lo = __float2bfloat16(v - __bfloat162float(hi));
        size_t o = ((size_t)e << 20) + (size_t)(n0 + ty + j * 8) * H + k0 + tx;
        g_wh[o] = hi;
        g_wl[o] = lo;
    }
}

// One warp per token: 8 logits, top-2, gates, compaction.
__global__ void router_k(const float* __restrict__ x, const float* __restrict__ Wg) {
    int gwarp = (blockIdx.x * blockDim.x + threadIdx.x) >> 5;
    int lane  = threadIdx.x & 31;
    if (gwarp >= T_TOK) return;
    const float* xr = x + (size_t)gwarp * H;

    float acc[E];
#pragma unroll
    for (int e = 0; e < E; e++) acc[e] = 0.f;
#pragma unroll 4
    for (int i = 0; i < H / 32; i++) {
        int h = lane + i * 32;
        float xv = __ldg(&xr[h]);
        float4 w0 = *(const float4*)&Wg[h * E];
        float4 w1 = *(const float4*)&Wg[h * E + 4];
        acc[0] = fmaf(xv, w0.x, acc[0]); acc[1] = fmaf(xv, w0.y, acc[1]);
        acc[2] = fmaf(xv, w0.z, acc[2]); acc[3] = fmaf(xv, w0.w, acc[3]);
        acc[4] = fmaf(xv, w1.x, acc[4]); acc[5] = fmaf(xv, w1.y, acc[5]);
        acc[6] = fmaf(xv, w1.z, acc[6]); acc[7] = fmaf(xv, w1.w, acc[7]);
    }
#pragma unroll
    for (int e = 0; e < E; e++)
#pragma unroll
        for (int o = 16; o > 0; o >>= 1)
            acc[e] += __shfl_xor_sync(0xffffffffu, acc[e], o);

    if (lane == 0) {
        int i0 = 0;
#pragma unroll
        for (int e = 1; e < E; e++) if (acc[e] > acc[i0]) i0 = e;
        int i1 = (i0 == 0) ? 1 : 0;
#pragma unroll
        for (int e = 0; e < E; e++) {
            if (e == i0) continue;
            if (acc[e] > acc[i1]) i1 = e;
        }
        float d  = expf(acc[i1] - acc[i0]);
        float s  = 1.f + d;
        int p0 = atomicAdd(&d_counts[i0], 1);
        d_tok[i0 * MAXR + p0]  = gwarp;
        d_gate[i0 * MAXR + p0] = 1.f / s;
        int p1 = atomicAdd(&d_counts[i1], 1);
        d_tok[i1 * MAXR + p1]  = gwarp;
        d_gate[i1 * MAXR + p1] = d / s;
    }
}

// ---------------- HMMA gathered expert GEMM ----------------
// C[128,128] = Ah@Bh + Ah@Bl + Al@Bh (bf16 hi/lo split, fp32 acc), scatter gate*(C+be).
__global__ __launch_bounds__(256)
void expert_gemm_hmma(const float* __restrict__ be, float* __restrict__ out) {
    const int e   = blockIdx.z;
    const int cnt = d_counts[e];
    const int m0  = blockIdx.y * 128;
    if (m0 >= cnt) return;
    const int n0  = blockIdx.x * 128;

    __shared__ __align__(16) unsigned char smA[2][128 * SMSTRIDE];
    __shared__ __align__(16) unsigned char smB[2][128 * SMSTRIDE];
    __shared__ int   toks[128];
    __shared__ float gts[128];

    const int tid  = threadIdx.x;
    const int lane = tid & 31;
    const int wid  = tid >> 5;
    const int wy   = wid & 3;    // M dim: 4 warps x 32 rows
    const int wx   = wid >> 2;   // N dim: 2 warps x 64 cols

    if (tid < 128) {
        int r = m0 + tid;
        toks[tid] = (r < cnt) ? d_tok[e * MAXR + r]  : -1;
        gts[tid]  = (r < cnt) ? d_gate[e * MAXR + r] : 0.f;
    }
    __syncthreads();

    // each thread owns 2 fixed 16B chunks of A and of B per iteration
    const int ar0 = tid >> 2,        ac0 = tid & 3;
    const int ar1 = ar0 + 64,        ac1 = ac0;
    const int t0 = toks[ar0], t1 = toks[ar1];
    const size_t aoff0 = (size_t)(t0 < 0 ? 0 : t0) * H + ac0 * 8;
    const size_t aoff1 = (size_t)(t1 < 0 ? 0 : t1) * H + ac1 * 8;
    const size_t boff0 = ((size_t)e << 20) + (size_t)(n0 + ar0) * H + ac0 * 8;
    const size_t boff1 = ((size_t)e << 20) + (size_t)(n0 + ar1) * H + ac1 * 8;
    const unsigned so0 = ar0 * SMSTRIDE + ac0 * 16;
    const unsigned so1 = ar1 * SMSTRIDE + ac1 * 16;

    float acc[2][4][2][4];
#pragma unroll
    for (int i = 0; i < 2; i++)
#pragma unroll
        for (int j = 0; j < 4; j++)
#pragma unroll
            for (int s = 0; s < 2; s++)
#pragma unroll
                for (int q = 0; q < 4; q++) acc[i][j][s][q] = 0.f;

    const unsigned aBase = smem_u32(smA[0]);
    const unsigned bBase = smem_u32(smB[0]);
    const unsigned bufSz = 128 * SMSTRIDE;
    const unsigned lmRow = lane & 15;     // ldmatrix row within 16
    const unsigned lmHi  = lane >> 4;     // 16B chunk select

    uint4 ra0, ra1, rb0, rb1;
    const uint4 z4 = make_uint4(0u, 0u, 0u, 0u);

    auto gload = [&](int it) {
        const __nv_bfloat16* pa = (it < 64) ? g_xh : g_xl;            // passes 0,1 -> xh
        const __nv_bfloat16* pb = ((it >> 5) == 1) ? g_wl : g_wh;     // pass 1 -> wl
        const int kk = (it & 31) * 32;
        ra0 = (t0 >= 0) ? __ldg((const uint4*)(pa + aoff0 + kk)) : z4;
        ra1 = (t1 >= 0) ? __ldg((const uint4*)(pa + aoff1 + kk)) : z4;
        rb0 = __ldg((const uint4*)(pb + boff0 + kk));
        rb1 = __ldg((const uint4*)(pb + boff1 + kk));
    };
    auto sstore = [&](int buf) {
        *(uint4*)(smA[buf] + so0) = ra0;
        *(uint4*)(smA[buf] + so1) = ra1;
        *(uint4*)(smB[buf] + so0) = rb0;
        *(uint4*)(smB[buf] + so1) = rb1;
    };
    auto compute = [&](int buf) {
        const unsigned ab = aBase + buf * bufSz;
        const unsigned bb = bBase + buf * bufSz;
#pragma unroll
        for (int ks = 0; ks < 2; ks++) {
            unsigned a[2][4];
#pragma unroll
            for (int i = 0; i < 2; i++)
                ldmatrix_x4(a[i], ab + (wy * 32 + i * 16 + lmRow) * SMSTRIDE
                                     + (ks * 2 + lmHi) * 16);
#pragma unroll
            for (int j = 0; j < 4; j++) {
                unsigned b[4];
                ldmatrix_x4(b, bb + (wx * 64 + j * 16 + lmRow) * SMSTRIDE
                                  + (ks * 2 + lmHi) * 16);
#pragma unroll
                for (int i = 0; i < 2; i++) {
                    mma_bf16(acc[i][j][0], a[i], b[0], b[2]);   // n8 rows j*16+0..7
                    mma_bf16(acc[i][j][1], a[i], b[1], b[3]);   // n8 rows j*16+8..15
                }
            }
        }
    };

    gload(0);
    sstore(0);
    __syncthreads();
#pragma unroll 1
    for (int it = 0; it < NITER; it++) {
        const int buf = it & 1;
        if (it + 1 < NITER) gload(it + 1);
        compute(buf);
        if (it + 1 < NITER) sstore(1 - buf);
        __syncthreads();
    }

    // epilogue: out[t][col] += gate * (acc + be[e][col]), 2 experts/token total
    const int qr = lane >> 2;       // 0..7
    const int qc = lane & 3;        // 0..3
    const float* beE = be + e * H;
#pragma unroll
    for (int i = 0; i < 2; i++) {
        const int rlo = wy * 32 + i * 16 + qr;
        const int rhi = rlo + 8;
        const int tlo = toks[rlo], thi = toks[rhi];
        const float glo = gts[rlo], ghi = gts[rhi];
        float* olo = out + (size_t)(tlo < 0 ? 0 : tlo) * H;
        float* ohi = out + (size_t)(thi < 0 ? 0 : thi) * H;
#pragma unroll
        for (int j = 0; j < 4; j++)
#pragma unroll
            for (int s = 0; s < 2; s++) {
                const int col = n0 + wx * 64 + j * 16 + s * 8 + qc * 2;
                const float b0 = __ldg(&beE[col]);
                const float b1 = __ldg(&beE[col + 1]);
                if (tlo >= 0) {
                    atomicAdd(&olo[col],     glo * (acc[i][j][s][0] + b0));
                    atomicAdd(&olo[col + 1], glo * (acc[i][j][s][1] + b1));
                }
                if (thi >= 0) {
                    atomicAdd(&ohi[col],     ghi * (acc[i][j][s][2] + b0));
                    atomicAdd(&ohi[col + 1], ghi * (acc[i][j][s][3] + b1));
                }
            }
    }
}

extern "C" void kernel_launch(void* const* d_in, const int* in_sizes, int n_in,
                              void* d_out, int out_size) {
    const float* x  = (const float*)d_in[0];   // (4,2048,1024)
    const float* Wg = (const float*)d_in[1];   // (1024, 8)
    const float* We = (const float*)d_in[2];   // (8, 1024, 1024)
    const float* be = (const float*)d_in[3];   // (8, 1024)
    float* out = (float*)d_out;

    cudaMemsetAsync(out, 0, (size_t)out_size * sizeof(float), 0);
    zero_counts_k<<<1, 32>>>();
    router_k<<<T_TOK / 8, 256>>>(x, Wg);
    convert_x_k<<<(T_TOK * H) / (256 * 4), 256>>>(x);
    convert_we_k<<<dim3(32, 32, E), dim3(32, 8)>>>(We);

    // grid: x = n-tile (8), y = m-tile (worst-case 64/expert), z = expert
    expert_gemm_hmma<<<dim3(H / 128, 64, E), 256>>>(be, out);
}

// round 9
// speedup vs baseline: 6.1648x; 2.2565x over previous
#include <cuda_runtime.h>
#include <cuda_fp16.h>
#include <math.h>
#include <stdint.h>

#define H 1024
#define E 8
#define T_TOK 8192
#define MAXR 16384
#define NITER 32            // single fp16 pass, 32 k-chunks (BK=32)
#define SMSTRIDE 80         // bytes per SMEM row (64B data + 16B pad, ldmatrix conflict-free)

// ---- device-global scratch (allocation-free rule) ----
__device__ int   d_counts[E];
__device__ int   d_tok[E * MAXR];
__device__ float d_gate[E * MAXR];
__device__ __half g_xh[(size_t)T_TOK * H];
__device__ __half g_wh[(size_t)E * H * H];   // transposed: [e][n][k]

__device__ __forceinline__ unsigned smem_u32(const void* p) {
    return (unsigned)__cvta_generic_to_shared(p);
}
__device__ __forceinline__ void ldmatrix_x4(unsigned r[4], unsigned addr) {
    asm volatile("ldmatrix.sync.aligned.m8n8.x4.shared.b16 {%0,%1,%2,%3}, [%4];"
                 : "=r"(r[0]), "=r"(r[1]), "=r"(r[2]), "=r"(r[3]) : "r"(addr));
}
__device__ __forceinline__ void mma_fp16(float d[4], const unsigned a[4],
                                         unsigned b0, unsigned b1) {
    asm volatile(
        "mma.sync.aligned.m16n8k16.row.col.f32.f16.f16.f32 "
        "{%0,%1,%2,%3}, {%4,%5,%6,%7}, {%8,%9}, {%0,%1,%2,%3};"
        : "+f"(d[0]), "+f"(d[1]), "+f"(d[2]), "+f"(d[3])
        : "r"(a[0]), "r"(a[1]), "r"(a[2]), "r"(a[3]), "r"(b0), "r"(b1));
}

// ---------------- small kernels ----------------
__global__ void zero_counts_k() {
    if (threadIdx.x < E) d_counts[threadIdx.x] = 0;
}

__global__ void convert_x_k(const float* __restrict__ x) {
    size_t i = ((size_t)blockIdx.x * blockDim.x + threadIdx.x) * 4;
    float4 v = *(const float4*)(x + i);
    __half h[4] = {__float2half_rn(v.x), __float2half_rn(v.y),
                   __float2half_rn(v.z), __float2half_rn(v.w)};
    *(uint2*)&g_xh[i] = *(uint2*)h;
}

// We[e][k][n] fp32 -> g_wh[e][n][k] fp16 (tiled transpose)
__global__ void convert_we_k(const float* __restrict__ We) {
    __shared__ float t[32][33];
    int e = blockIdx.z, n0 = blockIdx.x * 32, k0 = blockIdx.y * 32;
    const float* W = We + ((size_t)e << 20);
    int tx = threadIdx.x, ty = threadIdx.y;
#pragma unroll
    for (int j = 0; j < 4; j++)
        t[ty + j * 8][tx] = W[(size_t)(k0 + ty + j * 8) * H + n0 + tx];
    __syncthreads();
#pragma unroll
    for (int j = 0; j < 4; j++) {
        size_t o = ((size_t)e << 20) + (size_t)(n0 + ty + j * 8) * H + k0 + tx;
        g_wh[o] = __float2half_rn(t[tx][ty + j * 8]);
    }
}

// One warp per token: 8 logits, top-2, gates, compaction. (fp32, unchanged)
__global__ void router_k(const float* __restrict__ x, const float* __restrict__ Wg) {
    int gwarp = (blockIdx.x * blockDim.x + threadIdx.x) >> 5;
    int lane  = threadIdx.x & 31;
    if (gwarp >= T_TOK) return;
    const float* xr = x + (size_t)gwarp * H;

    float acc[E];
#pragma unroll
    for (int e = 0; e < E; e++) acc[e] = 0.f;
#pragma unroll 4
    for (int i = 0; i < H / 32; i++) {
        int h = lane + i * 32;
        float xv = __ldg(&xr[h]);
        float4 w0 = *(const float4*)&Wg[h * E];
        float4 w1 = *(const float4*)&Wg[h * E + 4];
        acc[0] = fmaf(xv, w0.x, acc[0]); acc[1] = fmaf(xv, w0.y, acc[1]);
        acc[2] = fmaf(xv, w0.z, acc[2]); acc[3] = fmaf(xv, w0.w, acc[3]);
        acc[4] = fmaf(xv, w1.x, acc[4]); acc[5] = fmaf(xv, w1.y, acc[5]);
        acc[6] = fmaf(xv, w1.z, acc[6]); acc[7] = fmaf(xv, w1.w, acc[7]);
    }
#pragma unroll
    for (int e = 0; e < E; e++)
#pragma unroll
        for (int o = 16; o > 0; o >>= 1)
            acc[e] += __shfl_xor_sync(0xffffffffu, acc[e], o);

    if (lane == 0) {
        int i0 = 0;
#pragma unroll
        for (int e = 1; e < E; e++) if (acc[e] > acc[i0]) i0 = e;
        int i1 = (i0 == 0) ? 1 : 0;
#pragma unroll
        for (int e = 0; e < E; e++) {
            if (e == i0) continue;
            if (acc[e] > acc[i1]) i1 = e;
        }
        float d  = expf(acc[i1] - acc[i0]);
        float s  = 1.f + d;
        int p0 = atomicAdd(&d_counts[i0], 1);
        d_tok[i0 * MAXR + p0]  = gwarp;
        d_gate[i0 * MAXR + p0] = 1.f / s;
        int p1 = atomicAdd(&d_counts[i1], 1);
        d_tok[i1 * MAXR + p1]  = gwarp;
        d_gate[i1 * MAXR + p1] = d / s;
    }
}

// ---------------- HMMA gathered expert GEMM (fp16 single pass) ----------------
__global__ __launch_bounds__(256)
void expert_gemm_hmma(const float* __restrict__ be, float* __restrict__ out) {
    const int e   = blockIdx.z;
    const int cnt = d_counts[e];
    const int m0  = blockIdx.y * 128;
    if (m0 >= cnt) return;
    const int n0  = blockIdx.x * 128;

    __shared__ __align__(16) unsigned char smA[2][128 * SMSTRIDE];
    __shared__ __align__(16) unsigned char smB[2][128 * SMSTRIDE];
    __shared__ int   toks[128];
    __shared__ float gts[128];

    const int tid  = threadIdx.x;
    const int lane = tid & 31;
    const int wid  = tid >> 5;
    const int wy   = wid & 3;    // M dim: 4 warps x 32 rows
    const int wx   = wid >> 2;   // N dim: 2 warps x 64 cols

    if (tid < 128) {
        int r = m0 + tid;
        toks[tid] = (r < cnt) ? d_tok[e * MAXR + r]  : -1;
        gts[tid]  = (r < cnt) ? d_gate[e * MAXR + r] : 0.f;
    }
    __syncthreads();

    // each thread owns 2 fixed 16B chunks of A and of B per iteration
    const int ar0 = tid >> 2,        ac0 = tid & 3;
    const int ar1 = ar0 + 64,        ac1 = ac0;
    const int t0 = toks[ar0], t1 = toks[ar1];
    const size_t aoff0 = (size_t)(t0 < 0 ? 0 : t0) * H + ac0 * 8;
    const size_t aoff1 = (size_t)(t1 < 0 ? 0 : t1) * H + ac1 * 8;
    const size_t boff0 = ((size_t)e << 20) + (size_t)(n0 + ar0) * H + ac0 * 8;
    const size_t boff1 = ((size_t)e << 20) + (size_t)(n0 + ar1) * H + ac1 * 8;
    const unsigned so0 = ar0 * SMSTRIDE + ac0 * 16;
    const unsigned so1 = ar1 * SMSTRIDE + ac1 * 16;

    float acc[2][4][2][4];
#pragma unroll
    for (int i = 0; i < 2; i++)
#pragma unroll
        for (int j = 0; j < 4; j++)
#pragma unroll
            for (int s = 0; s < 2; s++)
#pragma unroll
                for (int q = 0; q < 4; q++) acc[i][j][s][q] = 0.f;

    const unsigned aBase = smem_u32(smA[0]);
    const unsigned bBase = smem_u32(smB[0]);
    const unsigned bufSz = 128 * SMSTRIDE;
    const unsigned lmRow = lane & 15;
    const unsigned lmHi  = lane >> 4;

    uint4 ra0, ra1, rb0, rb1;
    const uint4 z4 = make_uint4(0u, 0u, 0u, 0u);

    auto gload = [&](int it) {
        const int kk = it * 32;
        ra0 = (t0 >= 0) ? __ldg((const uint4*)(g_xh + aoff0 + kk)) : z4;
        ra1 = (t1 >= 0) ? __ldg((const uint4*)(g_xh + aoff1 + kk)) : z4;
        rb0 = __ldg((const uint4*)(g_wh + boff0 + kk));
        rb1 = __ldg((const uint4*)(g_wh + boff1 + kk));
    };
    auto sstore = [&](int buf) {
        *(uint4*)(smA[buf] + so0) = ra0;
        *(uint4*)(smA[buf] + so1) = ra1;
        *(uint4*)(smB[buf] + so0) = rb0;
        *(uint4*)(smB[buf] + so1) = rb1;
    };
    auto compute = [&](int buf) {
        const unsigned ab = aBase + buf * bufSz;
        const unsigned bb = bBase + buf * bufSz;
#pragma unroll
        for (int ks = 0; ks < 2; ks++) {
            unsigned a[2][4];
#pragma unroll
            for (int i = 0; i < 2; i++)
                ldmatrix_x4(a[i], ab + (wy * 32 + i * 16 + lmRow) * SMSTRIDE
                                     + (ks * 2 + lmHi) * 16);
#pragma unroll
            for (int j = 0; j < 4; j++) {
                unsigned b[4];
                ldmatrix_x4(b, bb + (wx * 64 + j * 16 + lmRow) * SMSTRIDE
                                  + (ks * 2 + lmHi) * 16);
#pragma unroll
                for (int i = 0; i < 2; i++) {
                    mma_fp16(acc[i][j][0], a[i], b[0], b[2]);
                    mma_fp16(acc[i][j][1], a[i], b[1], b[3]);
                }
            }
        }
    };

    gload(0);
    sstore(0);
    __syncthreads();
#pragma unroll 1
    for (int it = 0; it < NITER; it++) {
        const int buf = it & 1;
        if (it + 1 < NITER) gload(it + 1);
        compute(buf);
        if (it + 1 < NITER) sstore(1 - buf);
        __syncthreads();
    }

    // epilogue: out[t][col] += gate * (acc + be[e][col])
    const int qr = lane >> 2;
    const int qc = lane & 3;
    const float* beE = be + e * H;
#pragma unroll
    for (int i = 0; i < 2; i++) {
        const int rlo = wy * 32 + i * 16 + qr;
        const int rhi = rlo + 8;
        const int tlo = toks[rlo], thi = toks[rhi];
        const float glo = gts[rlo], ghi = gts[rhi];
        float* olo = out + (size_t)(tlo < 0 ? 0 : tlo) * H;
        float* ohi = out + (size_t)(thi < 0 ? 0 : thi) * H;
#pragma unroll
        for (int j = 0; j < 4; j++)
#pragma unroll
            for (int s = 0; s < 2; s++) {
                const int col = n0 + wx * 64 + j * 16 + s * 8 + qc * 2;
                const float b0 = __ldg(&beE[col]);
                const float b1 = __ldg(&beE[col + 1]);
                if (tlo >= 0) {
                    atomicAdd(&olo[col],     glo * (acc[i][j][s][0] + b0));
                    atomicAdd(&olo[col + 1], glo * (acc[i][j][s][1] + b1));
                }
                if (thi >= 0) {
                    atomicAdd(&ohi[col],     ghi * (acc[i][j][s][2] + b0));
                    atomicAdd(&ohi[col + 1], ghi * (acc[i][j][s][3] + b1));
                }
            }
    }
}

extern "C" void kernel_launch(void* const* d_in, const int* in_sizes, int n_in,
                              void* d_out, int out_size) {
    const float* x  = (const float*)d_in[0];   // (4,2048,1024)
    const float* Wg = (const float*)d_in[1];   // (1024, 8)
    const float* We = (const float*)d_in[2];   // (8, 1024, 1024)
    const float* be = (const float*)d_in[3];   // (8, 1024)
    float* out = (float*)d_out;

    cudaMemsetAsync(out, 0, (size_t)out_size * sizeof(float), 0);
    zero_counts_k<<<1, 32>>>();
    router_k<<<T_TOK / 8, 256>>>(x, Wg);
    convert_x_k<<<(T_TOK * H) / (256 * 4), 256>>>(x);
    convert_we_k<<<dim3(32, 32, E), dim3(32, 8)>>>(We);

    // grid: x = n-tile (8), y = m-tile (worst-case 64/expert), z = expert
    expert_gemm_hmma<<<dim3(H / 128, 64, E), 256>>>(be, out);
}

// round 10
// speedup vs baseline: 6.7652x; 1.0974x over previous
#include <cuda_runtime.h>
#include <cuda_fp16.h>
#include <math.h>
#include <stdint.h>

#define H 1024
#define E 8
#define T_TOK 8192
#define MAXR 16384
#define NITER 32            // single fp16 pass, 32 k-chunks (BK=32)
#define SMSTRIDE 80         // bytes per SMEM row (64B data + 16B pad, ldmatrix conflict-free)
#define STAGES 3

// ---- device-global scratch (allocation-free rule) ----
__device__ int   d_counts[E];
__device__ int   d_tok[E * MAXR];
__device__ float d_gate[E * MAXR];
__device__ __half g_xh[(size_t)T_TOK * H];
__device__ __half g_wh[(size_t)E * H * H];   // transposed: [e][n][k]

__device__ __forceinline__ unsigned smem_u32(const void* p) {
    return (unsigned)__cvta_generic_to_shared(p);
}
__device__ __forceinline__ void ldmatrix_x4(unsigned r[4], unsigned addr) {
    asm volatile("ldmatrix.sync.aligned.m8n8.x4.shared.b16 {%0,%1,%2,%3}, [%4];"
                 : "=r"(r[0]), "=r"(r[1]), "=r"(r[2]), "=r"(r[3]) : "r"(addr));
}
__device__ __forceinline__ void mma_fp16(float d[4], const unsigned a[4],
                                         unsigned b0, unsigned b1) {
    asm volatile(
        "mma.sync.aligned.m16n8k16.row.col.f32.f16.f16.f32 "
        "{%0,%1,%2,%3}, {%4,%5,%6,%7}, {%8,%9}, {%0,%1,%2,%3};"
        : "+f"(d[0]), "+f"(d[1]), "+f"(d[2]), "+f"(d[3])
        : "r"(a[0]), "r"(a[1]), "r"(a[2]), "r"(a[3]), "r"(b0), "r"(b1));
}
__device__ __forceinline__ void cp16(unsigned dst, const void* src, int src_bytes) {
    asm volatile("cp.async.cg.shared.global [%0], [%1], 16, %2;"
                 :: "r"(dst), "l"(src), "r"(src_bytes) : "memory");
}
__device__ __forceinline__ void cp_commit() {
    asm volatile("cp.async.commit_group;" ::: "memory");
}
__device__ __forceinline__ void cp_wait1() {
    asm volatile("cp.async.wait_group 1;" ::: "memory");
}

// ---------------- convert_we (+ zero counts) ----------------
// We[e][k][n] fp32 -> g_wh[e][n][k] fp16 (tiled transpose); block (0,0,0) zeroes counts.
__global__ void convert_we_k(const float* __restrict__ We) {
    __shared__ float t[32][33];
    if (blockIdx.x == 0 && blockIdx.y == 0 && blockIdx.z == 0 &&
        threadIdx.y == 0 && threadIdx.x < E)
        d_counts[threadIdx.x] = 0;
    int e = blockIdx.z, n0 = blockIdx.x * 32, k0 = blockIdx.y * 32;
    const float* W = We + ((size_t)e << 20);
    int tx = threadIdx.x, ty = threadIdx.y;
#pragma unroll
    for (int j = 0; j < 4; j++)
        t[ty + j * 8][tx] = W[(size_t)(k0 + ty + j * 8) * H + n0 + tx];
    __syncthreads();
#pragma unroll
    for (int j = 0; j < 4; j++) {
        size_t o = ((size_t)e << 20) + (size_t)(n0 + ty + j * 8) * H + k0 + tx;
        g_wh[o] = __float2half_rn(t[tx][ty + j * 8]);
    }
}

// ---------------- fused router + x->fp16 convert ----------------
// One warp per token: 8 logits, top-2, gates, compaction; lanes also emit g_xh.
__global__ void router_k(const float* __restrict__ x, const float* __restrict__ Wg) {
    int gwarp = (blockIdx.x * blockDim.x + threadIdx.x) >> 5;
    int lane  = threadIdx.x & 31;
    if (gwarp >= T_TOK) return;
    const float* xr = x + (size_t)gwarp * H;
    __half* xh = g_xh + (size_t)gwarp * H;

    float acc[E];
#pragma unroll
    for (int e = 0; e < E; e++) acc[e] = 0.f;
#pragma unroll 4
    for (int i = 0; i < H / 32; i++) {
        int h = lane + i * 32;
        float xv = __ldg(&xr[h]);
        xh[h] = __float2half_rn(xv);              // fused convert_x
        float4 w0 = *(const float4*)&Wg[h * E];
        float4 w1 = *(const float4*)&Wg[h * E + 4];
        acc[0] = fmaf(xv, w0.x, acc[0]); acc[1] = fmaf(xv, w0.y, acc[1]);
        acc[2] = fmaf(xv, w0.z, acc[2]); acc[3] = fmaf(xv, w0.w, acc[3]);
        acc[4] = fmaf(xv, w1.x, acc[4]); acc[5] = fmaf(xv, w1.y, acc[5]);
        acc[6] = fmaf(xv, w1.z, acc[6]); acc[7] = fmaf(xv, w1.w, acc[7]);
    }
#pragma unroll
    for (int e = 0; e < E; e++)
#pragma unroll
        for (int o = 16; o > 0; o >>= 1)
            acc[e] += __shfl_xor_sync(0xffffffffu, acc[e], o);

    if (lane == 0) {
        int i0 = 0;
#pragma unroll
        for (int e = 1; e < E; e++) if (acc[e] > acc[i0]) i0 = e;
        int i1 = (i0 == 0) ? 1 : 0;
#pragma unroll
        for (int e = 0; e < E; e++) {
            if (e == i0) continue;
            if (acc[e] > acc[i1]) i1 = e;
        }
        float d  = expf(acc[i1] - acc[i0]);
        float s  = 1.f + d;
        int p0 = atomicAdd(&d_counts[i0], 1);
        d_tok[i0 * MAXR + p0]  = gwarp;
        d_gate[i0 * MAXR + p0] = 1.f / s;
        int p1 = atomicAdd(&d_counts[i1], 1);
        d_tok[i1 * MAXR + p1]  = gwarp;
        d_gate[i1 * MAXR + p1] = d / s;
    }
}

// ---------------- HMMA gathered expert GEMM (fp16, cp.async 3-stage) ----------------
__global__ __launch_bounds__(256)
void expert_gemm_hmma(const float* __restrict__ be, float* __restrict__ out) {
    const int e   = blockIdx.z;
    const int cnt = d_counts[e];
    const int m0  = blockIdx.y * 128;
    if (m0 >= cnt) return;
    const int n0  = blockIdx.x * 128;

    __shared__ __align__(16) unsigned char smA[STAGES][128 * SMSTRIDE];
    __shared__ __align__(16) unsigned char smB[STAGES][128 * SMSTRIDE];
    __shared__ int   toks[128];
    __shared__ float gts[128];

    const int tid  = threadIdx.x;
    const int lane = tid & 31;
    const int wid  = tid >> 5;
    const int wy   = wid & 3;    // M dim: 4 warps x 32 rows
    const int wx   = wid >> 2;   // N dim: 2 warps x 64 cols

    if (tid < 128) {
        int r = m0 + tid;
        toks[tid] = (r < cnt) ? d_tok[e * MAXR + r]  : -1;
        gts[tid]  = (r < cnt) ? d_gate[e * MAXR + r] : 0.f;
    }
    __syncthreads();

    // each thread owns 2 fixed 16B chunks of A and of B per k-chunk
    const int ar0 = tid >> 2,        ac0 = tid & 3;
    const int ar1 = ar0 + 64;
    const int t0 = toks[ar0], t1 = toks[ar1];
    const __half* pa0 = g_xh + (size_t)(t0 < 0 ? 0 : t0) * H + ac0 * 8;
    const __half* pa1 = g_xh + (size_t)(t1 < 0 ? 0 : t1) * H + ac0 * 8;
    const __half* pb0 = g_wh + ((size_t)e << 20) + (size_t)(n0 + ar0) * H + ac0 * 8;
    const __half* pb1 = g_wh + ((size_t)e << 20) + (size_t)(n0 + ar1) * H + ac0 * 8;
    const int sz0 = (t0 >= 0) ? 16 : 0;
    const int sz1 = (t1 >= 0) ? 16 : 0;
    const unsigned so0 = ar0 * SMSTRIDE + ac0 * 16;
    const unsigned so1 = ar1 * SMSTRIDE + ac0 * 16;

    float acc[2][4][2][4];
#pragma unroll
    for (int i = 0; i < 2; i++)
#pragma unroll
        for (int j = 0; j < 4; j++)
#pragma unroll
            for (int s = 0; s < 2; s++)
#pragma unroll
                for (int q = 0; q < 4; q++) acc[i][j][s][q] = 0.f;

    const unsigned aBase = smem_u32(smA[0]);
    const unsigned bBase = smem_u32(smB[0]);
    const unsigned bufSz = 128 * SMSTRIDE;
    const unsigned lmRow = lane & 15;
    const unsigned lmHi  = lane >> 4;

    auto issue = [&](int stage, int it) {
        const int kk = it * 32;
        const unsigned off = stage * bufSz;
        cp16(aBase + off + so0, pa0 + kk, sz0);
        cp16(aBase + off + so1, pa1 + kk, sz1);
        cp16(bBase + off + so0, pb0 + kk, 16);
        cp16(bBase + off + so1, pb1 + kk, 16);
    };
    auto compute = [&](int stage) {
        const unsigned ab = aBase + stage * bufSz;
        const unsigned bb = bBase + stage * bufSz;
#pragma unroll
        for (int ks = 0; ks < 2; ks++) {
            unsigned a[2][4];
#pragma unroll
            for (int i = 0; i < 2; i++)
                ldmatrix_x4(a[i], ab + (wy * 32 + i * 16 + lmRow) * SMSTRIDE
                                     + (ks * 2 + lmHi) * 16);
#pragma unroll
            for (int j = 0; j < 4; j++) {
                unsigned b[4];
                ldmatrix_x4(b, bb + (wx * 64 + j * 16 + lmRow) * SMSTRIDE
                                  + (ks * 2 + lmHi) * 16);
#pragma unroll
                for (int i = 0; i < 2; i++) {
                    mma_fp16(acc[i][j][0], a[i], b[0], b[2]);
                    mma_fp16(acc[i][j][1], a[i], b[1], b[3]);
                }
            }
        }
    };

    // prologue: stages 0,1 in flight
    issue(0, 0); cp_commit();
    issue(1, 1); cp_commit();

#pragma unroll 1
    for (int it = 0; it < NITER; it++) {
        cp_wait1();              // group for iter `it` complete (per-thread)
        __syncthreads();         // make all threads' stage-`it` data visible
        compute(it % STAGES);
        if (it + 2 < NITER) issue((it + 2) % STAGES, it + 2);
        cp_commit();             // empty groups near the tail keep counts aligned
    }

    // epilogue: out[t][col] += gate * (acc + be[e][col])
    const int qr = lane >> 2;
    const int qc = lane & 3;
    const float* beE = be + e * H;
#pragma unroll
    for (int i = 0; i < 2; i++) {
        const int rlo = wy * 32 + i * 16 + qr;
        const int rhi = rlo + 8;
        const int tlo = toks[rlo], thi = toks[rhi];
        const float glo = gts[rlo], ghi = gts[rhi];
        float* olo = out + (size_t)(tlo < 0 ? 0 : tlo) * H;
        float* ohi = out + (size_t)(thi < 0 ? 0 : thi) * H;
#pragma unroll
        for (int j = 0; j < 4; j++)
#pragma unroll
            for (int s = 0; s < 2; s++) {
                const int col = n0 + wx * 64 + j * 16 + s * 8 + qc * 2;
                const float b0 = __ldg(&beE[col]);
                const float b1 = __ldg(&beE[col + 1]);
                if (tlo >= 0) {
                    atomicAdd(&olo[col],     glo * (acc[i][j][s][0] + b0));
                    atomicAdd(&olo[col + 1], glo * (acc[i][j][s][1] + b1));
                }
                if (thi >= 0) {
                    atomicAdd(&ohi[col],     ghi * (acc[i][j][s][2] + b0));
                    atomicAdd(&ohi[col + 1], ghi * (acc[i][j][s][3] + b1));
                }
            }
    }
}

extern "C" void kernel_launch(void* const* d_in, const int* in_sizes, int n_in,
                              void* d_out, int out_size) {
    const float* x  = (const float*)d_in[0];   // (4,2048,1024)
    const float* Wg = (const float*)d_in[1];   // (1024, 8)
    const float* We = (const float*)d_in[2];   // (8, 1024, 1024)
    const float* be = (const float*)d_in[3];   // (8, 1024)
    float* out = (float*)d_out;

    cudaMemsetAsync(out, 0, (size_t)out_size * sizeof(float), 0);
    convert_we_k<<<dim3(32, 32, E), dim3(32, 8)>>>(We);   // also zeroes d_counts
    router_k<<<T_TOK / 8, 256>>>(x, Wg);                  // also emits g_xh

    // grid: x = n-tile (8), y = m-tile (worst-case 64/expert), z = expert
    expert_gemm_hmma<<<dim3(H / 128, 64, E), 256>>>(be, out);
}